// round 15
// baseline (speedup 1.0000x reference)
#include <cuda_runtime.h>
#include <cuda_fp16.h>
#include <math.h>
#include <mma.h>
using namespace nvcuda;

#define NN      20000
#define EE      320000
#define ETOT    (EE + NN)     // +self-loops
#define IN_DIM  128
#define HID     256
#define HEADS   4
#define OUT_DIM 128
#define PADROWS 128           // tile slack so wmma stores need no row guard

// ------------------- scratch (device globals) -------------------
__device__ float  g_h1 [(size_t)(NN + PADROWS) * HID];
__device__ __half g_h1h[(size_t)NN * HID];
__device__ float  g_out1[(size_t)(NN + PADROWS) * HID];
__device__ float  g_h2 [(size_t)(NN + PADROWS) * OUT_DIM];
__device__ __half g_h2h[(size_t)NN * OUT_DIM];
__device__ float  g_out2[(size_t)NN * OUT_DIM];

__device__ int g_srcA[ETOT], g_dstA[ETOT];
__device__ int g_cnt[NN];                    // zero at load; re-zeroed by k_apply2 tail
__device__ int g_off[NN + 1];
__device__ int g_pos[NN];
__device__ int g_csr[ETOT];

__device__ float g_as1[NN * HEADS], g_ad1[NN * HEADS];
__device__ float g_as2[NN], g_ad2[NN];
__device__ float g_sum[HID], g_sqs[HID];

__device__ __forceinline__ float lrelu(float v) { return v > 0.f ? v : 0.2f * v; }

// ------------------- decode + count (+detect, +zero BN accums) -------------------
__global__ void k_decode(const void* __restrict__ ei) {
    __shared__ int sh_is64;
    if (threadIdx.x == 0) {
        const unsigned long long* p = (const unsigned long long*)ei;
        int is64 = 1;
        for (int k = 0; k < 16; k++)
            if (p[k] >= (unsigned long long)NN) { is64 = 0; break; }
        sh_is64 = is64;
    }
    __syncthreads();
    int e = blockIdx.x * 256 + threadIdx.x;
    if (e < HID) { g_sum[e] = 0.f; g_sqs[e] = 0.f; }
    if (e >= ETOT) return;
    int s, d;
    if (e >= EE) { s = e - EE; d = e - EE; }
    else if (sh_is64) {
        const long long* p = (const long long*)ei;
        s = (int)p[e]; d = (int)p[EE + e];
    } else {
        const int* p = (const int*)ei;
        s = p[e]; d = p[EE + e];
    }
    g_srcA[e] = s; g_dstA[e] = d;
    atomicAdd(&g_cnt[d], 1);
}

// ------------------- coalesced scan: 1 block, 8 warps x 2500 elems -------------------
__global__ void k_scan() {
    __shared__ int wtot[8];
    int tid = threadIdx.x, lane = tid & 31, wid = tid >> 5;
    const int WCH = NN / 8;
    const int IT  = (WCH + 31) / 32;
    int base = wid * WCH;
    int tot = 0;
    for (int j = 0; j < IT; j++) {
        int o = j * 32 + lane;
        if (o < WCH) tot += g_cnt[base + o];
    }
    #pragma unroll
    for (int o = 16; o; o >>= 1) tot += __shfl_xor_sync(0xffffffffu, tot, o);
    if (lane == 0) wtot[wid] = tot;
    __syncthreads();
    if (tid == 0) {
        int run = 0;
        #pragma unroll
        for (int w = 0; w < 8; w++) { int t = wtot[w]; wtot[w] = run; run += t; }
        g_off[NN] = run;
    }
    __syncthreads();
    int run = wtot[wid];
    for (int j = 0; j < IT; j++) {
        int o = j * 32 + lane;
        int v = (o < WCH) ? g_cnt[base + o] : 0;
        int incl = v;
        #pragma unroll
        for (int s = 1; s < 32; s <<= 1) {
            int t = __shfl_up_sync(0xffffffffu, incl, s);
            if (lane >= s) incl += t;
        }
        if (o < WCH) {
            int off = run + incl - v;
            g_off[base + o] = off;
            g_pos[base + o] = off;
        }
        run += __shfl_sync(0xffffffffu, incl, 31);
    }
}

// ------------------- CSR fill, 1 edge/thread (measured best) -------------------
__global__ void k_fill() {
    int e = blockIdx.x * blockDim.x + threadIdx.x;
    if (e >= ETOT) return;
    int p = atomicAdd(&g_pos[g_dstA[e]], 1);
    g_csr[p] = g_srcA[e];
}

// ------------------- tf32 wmma GEMM: 128x64 tile, cvt hoisted to smem store -------------------
template<bool GUARD_A>
__device__ __forceinline__ void wgemm(const float* __restrict__ A,
                                      const float* __restrict__ B,
                                      float* __restrict__ C,
                                      int M, int K, int Nc) {
    __shared__ float As[128][40];
    __shared__ float Bs[32][72];
    int tid = threadIdx.x;
    int m0 = blockIdx.y * 128, n0 = blockIdx.x * 64;
    int w  = tid >> 5;
    int wm = w >> 1, wn = w & 1;

    wmma::fragment<wmma::accumulator, 16, 16, 8, float> acc[2][2];
    #pragma unroll
    for (int r = 0; r < 2; r++)
        #pragma unroll
        for (int c = 0; c < 2; c++) wmma::fill_fragment(acc[r][c], 0.f);

    for (int k0 = 0; k0 < K; k0 += 32) {
        #pragma unroll
        for (int i = 0; i < 4; i++) {
            int idx = tid + i * 256;
            int r = idx >> 3, c4 = (idx & 7) * 4;
            float4 v;
            if (!GUARD_A || (m0 + r) < M)
                v = *(const float4*)&A[(size_t)(m0 + r) * K + k0 + c4];
            else
                v = make_float4(0.f, 0.f, 0.f, 0.f);
            v.x = wmma::__float_to_tf32(v.x); v.y = wmma::__float_to_tf32(v.y);
            v.z = wmma::__float_to_tf32(v.z); v.w = wmma::__float_to_tf32(v.w);
            *(float4*)&As[r][c4] = v;
        }
        #pragma unroll
        for (int i = 0; i < 2; i++) {
            int idx = tid + i * 256;
            int r = idx >> 4, c4 = (idx & 15) * 4;
            float4 v = *(const float4*)&B[(size_t)(k0 + r) * Nc + n0 + c4];
            v.x = wmma::__float_to_tf32(v.x); v.y = wmma::__float_to_tf32(v.y);
            v.z = wmma::__float_to_tf32(v.z); v.w = wmma::__float_to_tf32(v.w);
            *(float4*)&Bs[r][c4] = v;
        }
        __syncthreads();
        #pragma unroll
        for (int kk = 0; kk < 32; kk += 8) {
            wmma::fragment<wmma::matrix_a, 16, 16, 8, wmma::precision::tf32, wmma::row_major> af[2];
            wmma::fragment<wmma::matrix_b, 16, 16, 8, wmma::precision::tf32, wmma::row_major> bf[2];
            #pragma unroll
            for (int r = 0; r < 2; r++)
                wmma::load_matrix_sync(af[r], &As[wm * 32 + r * 16][kk], 40);
            #pragma unroll
            for (int c = 0; c < 2; c++)
                wmma::load_matrix_sync(bf[c], &Bs[kk][wn * 32 + c * 16], 72);
            #pragma unroll
            for (int r = 0; r < 2; r++)
                #pragma unroll
                for (int c = 0; c < 2; c++)
                    wmma::mma_sync(acc[r][c], af[r], bf[c], acc[r][c]);
        }
        __syncthreads();
    }
    #pragma unroll
    for (int r = 0; r < 2; r++)
        #pragma unroll
        for (int c = 0; c < 2; c++)
            wmma::store_matrix_sync(&C[(size_t)(m0 + wm * 32 + r * 16) * Nc + n0 + wn * 32 + c * 16],
                                    acc[r][c], Nc, wmma::mem_row_major);
}
__global__ void k_gemm1(const float* __restrict__ x, const float* __restrict__ W1) {
    wgemm<true>(x, W1, g_h1, NN, IN_DIM, HID);
}
__global__ void k_gemm2(const float* __restrict__ W2) {
    wgemm<false>(g_out1, W2, g_h2, NN, HID, OUT_DIM);
}

// ------------------- attention logits (+ fp16 copy of h) -------------------
__global__ void k_alpha1(const float* __restrict__ asrc, const float* __restrict__ adst) {
    int warp = (blockIdx.x * blockDim.x + threadIdx.x) >> 5;
    int lane = threadIdx.x & 31;
    if (warp >= NN) return;
    const float* hrow = g_h1 + (size_t)warp * HID;
    __half* hout = g_h1h + (size_t)warp * HID;
    #pragma unroll
    for (int h = 0; h < HEADS; h++) {
        float x0 = hrow[h * 64 + lane], x1 = hrow[h * 64 + 32 + lane];
        hout[h * 64 + lane]      = __float2half_rn(x0);
        hout[h * 64 + 32 + lane] = __float2half_rn(x1);
        float vs = x0 * asrc[h * 64 + lane] + x1 * asrc[h * 64 + 32 + lane];
        float vd = x0 * adst[h * 64 + lane] + x1 * adst[h * 64 + 32 + lane];
        #pragma unroll
        for (int o = 16; o; o >>= 1) {
            vs += __shfl_down_sync(0xffffffffu, vs, o);
            vd += __shfl_down_sync(0xffffffffu, vd, o);
        }
        if (lane == 0) { g_as1[warp * HEADS + h] = vs; g_ad1[warp * HEADS + h] = vd; }
    }
}
__global__ void k_alpha2(const float* __restrict__ asrc, const float* __restrict__ adst) {
    if (blockIdx.x == 0 && threadIdx.x < HID) {       // zero BN accums for layer 2
        g_sum[threadIdx.x] = 0.f; g_sqs[threadIdx.x] = 0.f;
    }
    int warp = (blockIdx.x * blockDim.x + threadIdx.x) >> 5;
    int lane = threadIdx.x & 31;
    if (warp >= NN) return;
    const float* hrow = g_h2 + (size_t)warp * OUT_DIM;
    __half* hout = g_h2h + (size_t)warp * OUT_DIM;
    float vs = 0.f, vd = 0.f;
    #pragma unroll
    for (int j = 0; j < 4; j++) {
        float x0 = hrow[lane + 32 * j];
        hout[lane + 32 * j] = __float2half_rn(x0);
        vs += x0 * asrc[lane + 32 * j];
        vd += x0 * adst[lane + 32 * j];
    }
    #pragma unroll
    for (int o = 16; o; o >>= 1) {
        vs += __shfl_down_sync(0xffffffffu, vs, o);
        vd += __shfl_down_sync(0xffffffffu, vd, o);
    }
    if (lane == 0) { g_as2[warp] = vs; g_ad2[warp] = vd; }
}

// ------------------- layer-1 softmax+gather (fp16) + fused BN stats -------------------
// grid = 5000 blocks exactly (NN*2 warps), no tail -> safe __syncthreads
__global__ void k_agg1() {
    __shared__ float sh_sum[HID], sh_sqs[HID];
    { int t = threadIdx.x; sh_sum[t] = 0.f; sh_sqs[t] = 0.f; }
    __syncthreads();

    int gwarp = (blockIdx.x * blockDim.x + threadIdx.x) >> 5;
    int lane = threadIdx.x & 31;
    int node = gwarp >> 1, half = gwarp & 1;
    int beg = g_off[node], end = g_off[node + 1];
    float4 adv = *(const float4*)(g_ad1 + node * 4);

    float m0 = -1e30f, m1 = -1e30f, m2 = -1e30f, m3 = -1e30f;
    float d0 = 0.f, d1 = 0.f, d2 = 0.f, d3 = 0.f;
    for (int i = beg + lane; i < end; i += 32) {
        int s = g_csr[i];
        float4 a = *(const float4*)(g_as1 + s * 4);
        float v0 = lrelu(a.x + adv.x), v1 = lrelu(a.y + adv.y);
        float v2 = lrelu(a.z + adv.z), v3 = lrelu(a.w + adv.w);
        float n0 = fmaxf(m0, v0); d0 = d0 * __expf(m0 - n0) + __expf(v0 - n0); m0 = n0;
        float n1 = fmaxf(m1, v1); d1 = d1 * __expf(m1 - n1) + __expf(v1 - n1); m1 = n1;
        float n2 = fmaxf(m2, v2); d2 = d2 * __expf(m2 - n2) + __expf(v2 - n2); m2 = n2;
        float n3 = fmaxf(m3, v3); d3 = d3 * __expf(m3 - n3) + __expf(v3 - n3); m3 = n3;
    }
    #pragma unroll
    for (int o = 16; o; o >>= 1) {
        float mo, dd, mn;
        mo = __shfl_xor_sync(0xffffffffu, m0, o); dd = __shfl_xor_sync(0xffffffffu, d0, o);
        mn = fmaxf(m0, mo); d0 = d0 * __expf(m0 - mn) + dd * __expf(mo - mn); m0 = mn;
        mo = __shfl_xor_sync(0xffffffffu, m1, o); dd = __shfl_xor_sync(0xffffffffu, d1, o);
        mn = fmaxf(m1, mo); d1 = d1 * __expf(m1 - mn) + dd * __expf(mo - mn); m1 = mn;
        mo = __shfl_xor_sync(0xffffffffu, m2, o); dd = __shfl_xor_sync(0xffffffffu, d2, o);
        mn = fmaxf(m2, mo); d2 = d2 * __expf(m2 - mn) + dd * __expf(mo - mn); m2 = mn;
        mo = __shfl_xor_sync(0xffffffffu, m3, o); dd = __shfl_xor_sync(0xffffffffu, d3, o);
        mn = fmaxf(m3, mo); d3 = d3 * __expf(m3 - mn) + dd * __expf(mo - mn); m3 = mn;
    }

    int hsel = half * 2 + (lane >> 4);
    float ad_l  = hsel == 0 ? adv.x : hsel == 1 ? adv.y : hsel == 2 ? adv.z : adv.w;
    float m_l   = hsel == 0 ? m0 : hsel == 1 ? m1 : hsel == 2 ? m2 : m3;
    float den_l = hsel == 0 ? d0 : hsel == 1 ? d1 : hsel == 2 ? d2 : d3;
    float inv_l = 1.f / (den_l + 1e-16f);

    float4 acc = make_float4(0.f, 0.f, 0.f, 0.f);
    const uint2* __restrict__ h1h = (const uint2*)g_h1h;
    int fo = half * 32 + lane;                 // 4-channel chunk index in [0,64)
    for (int i = beg; i < end; i++) {
        int s = g_csr[i];
        float a = g_as1[(s << 2) + hsel];
        float c = __expf(lrelu(a + ad_l) - m_l) * inv_l;
        uint2 raw = h1h[(size_t)s * 64 + fo];
        float2 f0 = __half22float2(*(__half2*)&raw.x);
        float2 f1 = __half22float2(*(__half2*)&raw.y);
        acc.x += f0.x * c; acc.y += f0.y * c; acc.z += f1.x * c; acc.w += f1.y * c;
    }
    ((float4*)(g_out1 + (size_t)node * HID))[fo] = acc;

    // fused BN stats: block-local smem reduction, then per-channel global atomics
    int ch = fo * 4;
    atomicAdd(&sh_sum[ch + 0], acc.x); atomicAdd(&sh_sqs[ch + 0], acc.x * acc.x);
    atomicAdd(&sh_sum[ch + 1], acc.y); atomicAdd(&sh_sqs[ch + 1], acc.y * acc.y);
    atomicAdd(&sh_sum[ch + 2], acc.z); atomicAdd(&sh_sqs[ch + 2], acc.z * acc.z);
    atomicAdd(&sh_sum[ch + 3], acc.w); atomicAdd(&sh_sqs[ch + 3], acc.w * acc.w);
    __syncthreads();
    { int t = threadIdx.x; atomicAdd(&g_sum[t], sh_sum[t]); atomicAdd(&g_sqs[t], sh_sqs[t]); }
}

// ------------------- layer-2 softmax+gather (fp16) + fused BN stats -------------------
// grid = 2500 blocks exactly (NN warps), no tail
__global__ void k_agg2() {
    __shared__ float sh_sum[OUT_DIM], sh_sqs[OUT_DIM];
    if (threadIdx.x < OUT_DIM) { sh_sum[threadIdx.x] = 0.f; sh_sqs[threadIdx.x] = 0.f; }
    __syncthreads();

    int gw = (blockIdx.x * blockDim.x + threadIdx.x) >> 5;
    int lane = threadIdx.x & 31;
    int beg = g_off[gw], end = g_off[gw + 1];
    float ad = g_ad2[gw];

    float m = -1e30f, den = 0.f;
    for (int i = beg + lane; i < end; i += 32) {
        float v = lrelu(g_as2[g_csr[i]] + ad);
        float mn = fmaxf(m, v);
        den = den * __expf(m - mn) + __expf(v - mn);
        m = mn;
    }
    #pragma unroll
    for (int o = 16; o; o >>= 1) {
        float mo = __shfl_xor_sync(0xffffffffu, m, o);
        float dd = __shfl_xor_sync(0xffffffffu, den, o);
        float mn = fmaxf(m, mo);
        den = den * __expf(m - mn) + dd * __expf(mo - mn);
        m = mn;
    }
    float inv = 1.f / (den + 1e-16f);

    float4 acc = make_float4(0.f, 0.f, 0.f, 0.f);
    const uint2* __restrict__ h2h = (const uint2*)g_h2h;
    for (int i = beg; i < end; i++) {
        int s = g_csr[i];
        float c = __expf(lrelu(g_as2[s] + ad) - m) * inv;
        uint2 raw = h2h[(size_t)s * 32 + lane];
        float2 f0 = __half22float2(*(__half2*)&raw.x);
        float2 f1 = __half22float2(*(__half2*)&raw.y);
        acc.x += f0.x * c; acc.y += f0.y * c; acc.z += f1.x * c; acc.w += f1.y * c;
    }
    ((float4*)(g_out2 + (size_t)gw * OUT_DIM))[lane] = acc;

    int ch = lane * 4;
    atomicAdd(&sh_sum[ch + 0], acc.x); atomicAdd(&sh_sqs[ch + 0], acc.x * acc.x);
    atomicAdd(&sh_sum[ch + 1], acc.y); atomicAdd(&sh_sqs[ch + 1], acc.y * acc.y);
    atomicAdd(&sh_sum[ch + 2], acc.z); atomicAdd(&sh_sqs[ch + 2], acc.z * acc.z);
    atomicAdd(&sh_sum[ch + 3], acc.w); atomicAdd(&sh_sqs[ch + 3], acc.w * acc.w);
    __syncthreads();
    if (threadIdx.x < OUT_DIM) {
        atomicAdd(&g_sum[threadIdx.x], sh_sum[threadIdx.x]);
        atomicAdd(&g_sqs[threadIdx.x], sh_sqs[threadIdx.x]);
    }
}

// ------------------- batchnorm apply -------------------
__global__ void k_apply1(const float* __restrict__ gamma, const float* __restrict__ beta) {
    int i = blockIdx.x * blockDim.x + threadIdx.x;
    if (i >= NN * HID) return;
    int c = i & (HID - 1);
    float mean = g_sum[c] * (1.f / NN);
    float var = g_sqs[c] * (1.f / NN) - mean * mean;
    float v = (g_out1[i] - mean) * rsqrtf(var + 1e-5f) * gamma[c] + beta[c];
    g_out1[i] = v > 0.f ? v : (__expf(v) - 1.f);   // ELU
}
__global__ void k_apply2(const float* __restrict__ gamma, const float* __restrict__ beta,
                         float* __restrict__ out) {
    int i = blockIdx.x * blockDim.x + threadIdx.x;
    if (i < NN) g_cnt[i] = 0;                 // re-arm counts for next call
    if (i >= NN * OUT_DIM) return;
    int c = i & (OUT_DIM - 1);
    float mean = g_sum[c] * (1.f / NN);
    float var = g_sqs[c] * (1.f / NN) - mean * mean;
    out[i] = (g_out2[i] - mean) * rsqrtf(var + 1e-5f) * gamma[c] + beta[c];
}

// ------------------- launch -------------------
extern "C" void kernel_launch(void* const* d_in, const int* in_sizes, int n_in,
                              void* d_out, int out_size) {
    const float* x     = (const float*)d_in[0];
    const void*  ei    = d_in[1];
    const float* W1    = (const float*)d_in[2];
    const float* asrc1 = (const float*)d_in[3];
    const float* adst1 = (const float*)d_in[4];
    const float* g1    = (const float*)d_in[6];
    const float* b1    = (const float*)d_in[7];
    const float* W2    = (const float*)d_in[8];
    const float* asrc2 = (const float*)d_in[9];
    const float* adst2 = (const float*)d_in[10];
    const float* g2    = (const float*)d_in[12];
    const float* b2    = (const float*)d_in[13];
    float* out = (float*)d_out;

    const int T = 256;
    const int EB = (ETOT + T - 1) / T;

    k_decode<<<EB, T>>>(ei);                                   // decode + count + zero BN
    k_gemm1<<<dim3(HID / 64, (NN + 127) / 128), T>>>(x, W1);   // tf32 wmma
    k_scan<<<1, 256>>>();
    k_fill<<<EB, T>>>();
    k_alpha1<<<(NN * 32 + T - 1) / T, T>>>(asrc1, adst1);      // + fp16 copy of h1
    k_agg1<<<NN * 64 / T, T>>>();                              // fp16 gather + fused stats
    k_apply1<<<(NN * HID + T - 1) / T, T>>>(g1, b1);
    k_gemm2<<<dim3(OUT_DIM / 64, (NN + 127) / 128), T>>>(W2);  // tf32 wmma
    k_alpha2<<<(NN * 32 + T - 1) / T, T>>>(asrc2, adst2);      // + fp16 copy of h2 + zero BN
    k_agg2<<<NN * 32 / T, T>>>();                              // fp16 gather + fused stats
    k_apply2<<<(NN * OUT_DIM + T - 1) / T, T>>>(g2, b2, out);  // + re-zero g_cnt
}

// round 16
// speedup vs baseline: 1.0916x; 1.0916x over previous
#include <cuda_runtime.h>
#include <math.h>
#include <mma.h>
using namespace nvcuda;

#define NN      20000
#define EE      320000
#define ETOT    (EE + NN)     // +self-loops
#define IN_DIM  128
#define HID     256
#define HEADS   4
#define OUT_DIM 128
#define PADROWS 128           // tile slack so wmma stores need no row guard

// ------------------- scratch (device globals) -------------------
__device__ float g_h1[(size_t)(NN + PADROWS) * HID];
__device__ float g_out1[(size_t)(NN + PADROWS) * HID];
__device__ float g_h2[(size_t)(NN + PADROWS) * OUT_DIM];
__device__ float g_out2[(size_t)NN * OUT_DIM];

__device__ int g_srcA[ETOT], g_dstA[ETOT];
__device__ int g_rank[ETOT];                 // edge's arrival rank within its dst bucket
__device__ int g_cnt[NN];                    // zero at load; re-zeroed by k_apply2 tail
__device__ int g_off[NN + 1];
__device__ int g_csr[ETOT];

__device__ float g_as1[NN * HEADS], g_ad1[NN * HEADS];
__device__ float g_as2[NN], g_ad2[NN];
__device__ float g_sum[HID], g_sqs[HID];

__device__ __forceinline__ float lrelu(float v) { return v > 0.f ? v : 0.2f * v; }

// ------------------- decode + count (+detect, +zero BN accums, +rank) -------------------
__global__ void k_decode(const void* __restrict__ ei) {
    __shared__ int sh_is64;
    if (threadIdx.x == 0) {
        const unsigned long long* p = (const unsigned long long*)ei;
        int is64 = 1;
        for (int k = 0; k < 16; k++)
            if (p[k] >= (unsigned long long)NN) { is64 = 0; break; }
        sh_is64 = is64;
    }
    __syncthreads();
    int e = blockIdx.x * 256 + threadIdx.x;
    if (e < HID) { g_sum[e] = 0.f; g_sqs[e] = 0.f; }
    if (e >= ETOT) return;
    int s, d;
    if (e >= EE) { s = e - EE; d = e - EE; }
    else if (sh_is64) {
        const long long* p = (const long long*)ei;
        s = (int)p[e]; d = (int)p[EE + e];
    } else {
        const int* p = (const int*)ei;
        s = p[e]; d = p[EE + e];
    }
    g_srcA[e] = s; g_dstA[e] = d;
    g_rank[e] = atomicAdd(&g_cnt[d], 1);     // rank doubles as the CSR slot index
}

// ------------------- coalesced scan: 1 block, 8 warps x 2500 elems -------------------
__global__ void k_scan() {
    __shared__ int wtot[8];
    int tid = threadIdx.x, lane = tid & 31, wid = tid >> 5;
    const int WCH = NN / 8;
    const int IT  = (WCH + 31) / 32;
    int base = wid * WCH;
    int tot = 0;
    for (int j = 0; j < IT; j++) {
        int o = j * 32 + lane;
        if (o < WCH) tot += g_cnt[base + o];
    }
    #pragma unroll
    for (int o = 16; o; o >>= 1) tot += __shfl_xor_sync(0xffffffffu, tot, o);
    if (lane == 0) wtot[wid] = tot;
    __syncthreads();
    if (tid == 0) {
        int run = 0;
        #pragma unroll
        for (int w = 0; w < 8; w++) { int t = wtot[w]; wtot[w] = run; run += t; }
        g_off[NN] = run;
    }
    __syncthreads();
    int run = wtot[wid];
    for (int j = 0; j < IT; j++) {
        int o = j * 32 + lane;
        int v = (o < WCH) ? g_cnt[base + o] : 0;
        int incl = v;
        #pragma unroll
        for (int s = 1; s < 32; s <<= 1) {
            int t = __shfl_up_sync(0xffffffffu, incl, s);
            if (lane >= s) incl += t;
        }
        if (o < WCH) g_off[base + o] = run + incl - v;
        run += __shfl_sync(0xffffffffu, incl, 31);
    }
}

// ------------------- CSR fill: atomic-free (rank precomputed in decode) -------------------
__global__ void k_fill() {
    int e = blockIdx.x * blockDim.x + threadIdx.x;
    if (e >= ETOT) return;
    g_csr[g_off[g_dstA[e]] + g_rank[e]] = g_srcA[e];
}

// ------------------- tf32 wmma GEMM: 128x64 tile, cvt hoisted to smem store -------------------
template<bool GUARD_A>
__device__ __forceinline__ void wgemm(const float* __restrict__ A,
                                      const float* __restrict__ B,
                                      float* __restrict__ C,
                                      int M, int K, int Nc) {
    __shared__ float As[128][40];
    __shared__ float Bs[32][72];
    int tid = threadIdx.x;
    int m0 = blockIdx.y * 128, n0 = blockIdx.x * 64;
    int w  = tid >> 5;
    int wm = w >> 1, wn = w & 1;

    wmma::fragment<wmma::accumulator, 16, 16, 8, float> acc[2][2];
    #pragma unroll
    for (int r = 0; r < 2; r++)
        #pragma unroll
        for (int c = 0; c < 2; c++) wmma::fill_fragment(acc[r][c], 0.f);

    for (int k0 = 0; k0 < K; k0 += 32) {
        #pragma unroll
        for (int i = 0; i < 4; i++) {
            int idx = tid + i * 256;
            int r = idx >> 3, c4 = (idx & 7) * 4;
            float4 v;
            if (!GUARD_A || (m0 + r) < M)
                v = *(const float4*)&A[(size_t)(m0 + r) * K + k0 + c4];
            else
                v = make_float4(0.f, 0.f, 0.f, 0.f);
            v.x = wmma::__float_to_tf32(v.x); v.y = wmma::__float_to_tf32(v.y);
            v.z = wmma::__float_to_tf32(v.z); v.w = wmma::__float_to_tf32(v.w);
            *(float4*)&As[r][c4] = v;
        }
        #pragma unroll
        for (int i = 0; i < 2; i++) {
            int idx = tid + i * 256;
            int r = idx >> 4, c4 = (idx & 15) * 4;
            float4 v = *(const float4*)&B[(size_t)(k0 + r) * Nc + n0 + c4];
            v.x = wmma::__float_to_tf32(v.x); v.y = wmma::__float_to_tf32(v.y);
            v.z = wmma::__float_to_tf32(v.z); v.w = wmma::__float_to_tf32(v.w);
            *(float4*)&Bs[r][c4] = v;
        }
        __syncthreads();
        #pragma unroll
        for (int kk = 0; kk < 32; kk += 8) {
            wmma::fragment<wmma::matrix_a, 16, 16, 8, wmma::precision::tf32, wmma::row_major> af[2];
            wmma::fragment<wmma::matrix_b, 16, 16, 8, wmma::precision::tf32, wmma::row_major> bf[2];
            #pragma unroll
            for (int r = 0; r < 2; r++)
                wmma::load_matrix_sync(af[r], &As[wm * 32 + r * 16][kk], 40);
            #pragma unroll
            for (int c = 0; c < 2; c++)
                wmma::load_matrix_sync(bf[c], &Bs[kk][wn * 32 + c * 16], 72);
            #pragma unroll
            for (int r = 0; r < 2; r++)
                #pragma unroll
                for (int c = 0; c < 2; c++)
                    wmma::mma_sync(acc[r][c], af[r], bf[c], acc[r][c]);
        }
        __syncthreads();
    }
    #pragma unroll
    for (int r = 0; r < 2; r++)
        #pragma unroll
        for (int c = 0; c < 2; c++)
            wmma::store_matrix_sync(&C[(size_t)(m0 + wm * 32 + r * 16) * Nc + n0 + wn * 32 + c * 16],
                                    acc[r][c], Nc, wmma::mem_row_major);
}
__global__ void k_gemm1(const float* __restrict__ x, const float* __restrict__ W1) {
    wgemm<true>(x, W1, g_h1, NN, IN_DIM, HID);
}
__global__ void k_gemm2(const float* __restrict__ W2) {
    wgemm<false>(g_out1, W2, g_h2, NN, HID, OUT_DIM);
}

// ------------------- attention logits -------------------
__global__ void k_alpha1(const float* __restrict__ asrc, const float* __restrict__ adst) {
    int warp = (blockIdx.x * blockDim.x + threadIdx.x) >> 5;
    int lane = threadIdx.x & 31;
    if (warp >= NN) return;
    const float* hrow = g_h1 + (size_t)warp * HID;
    #pragma unroll
    for (int h = 0; h < HEADS; h++) {
        float x0 = hrow[h * 64 + lane], x1 = hrow[h * 64 + 32 + lane];
        float vs = x0 * asrc[h * 64 + lane] + x1 * asrc[h * 64 + 32 + lane];
        float vd = x0 * adst[h * 64 + lane] + x1 * adst[h * 64 + 32 + lane];
        #pragma unroll
        for (int o = 16; o; o >>= 1) {
            vs += __shfl_down_sync(0xffffffffu, vs, o);
            vd += __shfl_down_sync(0xffffffffu, vd, o);
        }
        if (lane == 0) { g_as1[warp * HEADS + h] = vs; g_ad1[warp * HEADS + h] = vd; }
    }
}
__global__ void k_alpha2(const float* __restrict__ asrc, const float* __restrict__ adst) {
    if (blockIdx.x == 0 && threadIdx.x < HID) {       // zero BN accums for layer 2
        g_sum[threadIdx.x] = 0.f; g_sqs[threadIdx.x] = 0.f;
    }
    int warp = (blockIdx.x * blockDim.x + threadIdx.x) >> 5;
    int lane = threadIdx.x & 31;
    if (warp >= NN) return;
    const float* hrow = g_h2 + (size_t)warp * OUT_DIM;
    float vs = 0.f, vd = 0.f;
    #pragma unroll
    for (int j = 0; j < 4; j++) {
        float x0 = hrow[lane + 32 * j];
        vs += x0 * asrc[lane + 32 * j];
        vd += x0 * adst[lane + 32 * j];
    }
    #pragma unroll
    for (int o = 16; o; o >>= 1) {
        vs += __shfl_down_sync(0xffffffffu, vs, o);
        vd += __shfl_down_sync(0xffffffffu, vd, o);
    }
    if (lane == 0) { g_as2[warp] = vs; g_ad2[warp] = vd; }
}

// ------------------- layer-1 softmax+gather: 2 warps per node, online softmax -------------------
__global__ void k_agg1() {
    int gwarp = (blockIdx.x * blockDim.x + threadIdx.x) >> 5;
    int lane = threadIdx.x & 31;
    int node = gwarp >> 1, half = gwarp & 1;
    if (node >= NN) return;
    int beg = g_off[node], end = g_off[node + 1];
    float4 adv = *(const float4*)(g_ad1 + node * 4);

    float m0 = -1e30f, m1 = -1e30f, m2 = -1e30f, m3 = -1e30f;
    float d0 = 0.f, d1 = 0.f, d2 = 0.f, d3 = 0.f;
    for (int i = beg + lane; i < end; i += 32) {
        int s = g_csr[i];
        float4 a = *(const float4*)(g_as1 + s * 4);
        float v0 = lrelu(a.x + adv.x), v1 = lrelu(a.y + adv.y);
        float v2 = lrelu(a.z + adv.z), v3 = lrelu(a.w + adv.w);
        float n0 = fmaxf(m0, v0); d0 = d0 * __expf(m0 - n0) + __expf(v0 - n0); m0 = n0;
        float n1 = fmaxf(m1, v1); d1 = d1 * __expf(m1 - n1) + __expf(v1 - n1); m1 = n1;
        float n2 = fmaxf(m2, v2); d2 = d2 * __expf(m2 - n2) + __expf(v2 - n2); m2 = n2;
        float n3 = fmaxf(m3, v3); d3 = d3 * __expf(m3 - n3) + __expf(v3 - n3); m3 = n3;
    }
    #pragma unroll
    for (int o = 16; o; o >>= 1) {
        float mo, dd, mn;
        mo = __shfl_xor_sync(0xffffffffu, m0, o); dd = __shfl_xor_sync(0xffffffffu, d0, o);
        mn = fmaxf(m0, mo); d0 = d0 * __expf(m0 - mn) + dd * __expf(mo - mn); m0 = mn;
        mo = __shfl_xor_sync(0xffffffffu, m1, o); dd = __shfl_xor_sync(0xffffffffu, d1, o);
        mn = fmaxf(m1, mo); d1 = d1 * __expf(m1 - mn) + dd * __expf(mo - mn); m1 = mn;
        mo = __shfl_xor_sync(0xffffffffu, m2, o); dd = __shfl_xor_sync(0xffffffffu, d2, o);
        mn = fmaxf(m2, mo); d2 = d2 * __expf(m2 - mn) + dd * __expf(mo - mn); m2 = mn;
        mo = __shfl_xor_sync(0xffffffffu, m3, o); dd = __shfl_xor_sync(0xffffffffu, d3, o);
        mn = fmaxf(m3, mo); d3 = d3 * __expf(m3 - mn) + dd * __expf(mo - mn); m3 = mn;
    }

    int hsel = half * 2 + (lane >> 4);
    float ad_l  = hsel == 0 ? adv.x : hsel == 1 ? adv.y : hsel == 2 ? adv.z : adv.w;
    float m_l   = hsel == 0 ? m0 : hsel == 1 ? m1 : hsel == 2 ? m2 : m3;
    float den_l = hsel == 0 ? d0 : hsel == 1 ? d1 : hsel == 2 ? d2 : d3;
    float inv_l = 1.f / (den_l + 1e-16f);

    float4 acc = make_float4(0.f, 0.f, 0.f, 0.f);
    const float4* __restrict__ h1v = (const float4*)g_h1;
    int fo = half * 32 + lane;
    for (int i = beg; i < end; i++) {
        int s = g_csr[i];
        float a = g_as1[(s << 2) + hsel];
        float c = __expf(lrelu(a + ad_l) - m_l) * inv_l;
        float4 v = h1v[(size_t)s * 64 + fo];
        acc.x += v.x * c; acc.y += v.y * c; acc.z += v.z * c; acc.w += v.w * c;
    }
    ((float4*)(g_out1 + (size_t)node * HID))[fo] = acc;
}

// ------------------- layer-2 softmax+gather, online softmax -------------------
__global__ void k_agg2() {
    int gw = (blockIdx.x * blockDim.x + threadIdx.x) >> 5;
    int lane = threadIdx.x & 31;
    if (gw >= NN) return;
    int beg = g_off[gw], end = g_off[gw + 1];
    float ad = g_ad2[gw];

    float m = -1e30f, den = 0.f;
    for (int i = beg + lane; i < end; i += 32) {
        float v = lrelu(g_as2[g_csr[i]] + ad);
        float mn = fmaxf(m, v);
        den = den * __expf(m - mn) + __expf(v - mn);
        m = mn;
    }
    #pragma unroll
    for (int o = 16; o; o >>= 1) {
        float mo = __shfl_xor_sync(0xffffffffu, m, o);
        float dd = __shfl_xor_sync(0xffffffffu, den, o);
        float mn = fmaxf(m, mo);
        den = den * __expf(m - mn) + dd * __expf(mo - mn);
        m = mn;
    }
    float inv = 1.f / (den + 1e-16f);

    float4 acc = make_float4(0.f, 0.f, 0.f, 0.f);
    const float4* __restrict__ h2v = (const float4*)g_h2;
    for (int i = beg; i < end; i++) {
        int s = g_csr[i];
        float c = __expf(lrelu(g_as2[s] + ad) - m) * inv;
        float4 v = h2v[(size_t)s * 32 + lane];
        acc.x += v.x * c; acc.y += v.y * c; acc.z += v.z * c; acc.w += v.w * c;
    }
    ((float4*)(g_out2 + (size_t)gw * OUT_DIM))[lane] = acc;
}

// ------------------- batchnorm -------------------
#define SROWS 80
__global__ void k_stats1() {
    int c = threadIdx.x;
    int r0 = blockIdx.x * SROWS;
    int rend = r0 + SROWS; if (rend > NN) rend = NN;
    float s = 0.f, s2 = 0.f;
    for (int r = r0; r < rend; r++) {
        float v = g_out1[(size_t)r * HID + c];
        s += v; s2 += v * v;
    }
    atomicAdd(&g_sum[c], s); atomicAdd(&g_sqs[c], s2);
}
// float4-vectorized BN apply + ELU (layer 1)
__global__ void k_apply1(const float* __restrict__ gamma, const float* __restrict__ beta) {
    int i4 = blockIdx.x * blockDim.x + threadIdx.x;
    if (i4 >= NN * HID / 4) return;
    int c4 = (i4 & (HID / 4 - 1)) * 4;
    float4 sm = *(const float4*)&g_sum[c4];
    float4 sq = *(const float4*)&g_sqs[c4];
    float4 ga = *(const float4*)&gamma[c4];
    float4 be = *(const float4*)&beta[c4];
    float4 v = *(float4*)&g_out1[(size_t)i4 * 4];
    float mean, var, sc;
    mean = sm.x / NN; var = sq.x / NN - mean * mean; sc = rsqrtf(var + 1e-5f) * ga.x;
    v.x = (v.x - mean) * sc + be.x; v.x = v.x > 0.f ? v.x : (__expf(v.x) - 1.f);
    mean = sm.y / NN; var = sq.y / NN - mean * mean; sc = rsqrtf(var + 1e-5f) * ga.y;
    v.y = (v.y - mean) * sc + be.y; v.y = v.y > 0.f ? v.y : (__expf(v.y) - 1.f);
    mean = sm.z / NN; var = sq.z / NN - mean * mean; sc = rsqrtf(var + 1e-5f) * ga.z;
    v.z = (v.z - mean) * sc + be.z; v.z = v.z > 0.f ? v.z : (__expf(v.z) - 1.f);
    mean = sm.w / NN; var = sq.w / NN - mean * mean; sc = rsqrtf(var + 1e-5f) * ga.w;
    v.w = (v.w - mean) * sc + be.w; v.w = v.w > 0.f ? v.w : (__expf(v.w) - 1.f);
    *(float4*)&g_out1[(size_t)i4 * 4] = v;
}
__global__ void k_stats2() {
    int c = threadIdx.x;
    int r0 = blockIdx.x * SROWS;
    int rend = r0 + SROWS; if (rend > NN) rend = NN;
    float s = 0.f, s2 = 0.f;
    for (int r = r0; r < rend; r++) {
        float v = g_out2[(size_t)r * OUT_DIM + c];
        s += v; s2 += v * v;
    }
    atomicAdd(&g_sum[c], s); atomicAdd(&g_sqs[c], s2);
}
// float4-vectorized BN apply (layer 2) -> out; re-zeros g_cnt
__global__ void k_apply2(const float* __restrict__ gamma, const float* __restrict__ beta,
                         float* __restrict__ out) {
    int i4 = blockIdx.x * blockDim.x + threadIdx.x;
    if (i4 < NN) g_cnt[i4] = 0;               // re-arm counts for next call
    if (i4 >= NN * OUT_DIM / 4) return;
    int c4 = (i4 & (OUT_DIM / 4 - 1)) * 4;
    float4 sm = *(const float4*)&g_sum[c4];
    float4 sq = *(const float4*)&g_sqs[c4];
    float4 ga = *(const float4*)&gamma[c4];
    float4 be = *(const float4*)&beta[c4];
    float4 v = *(const float4*)&g_out2[(size_t)i4 * 4];
    float mean, var, sc;
    mean = sm.x / NN; var = sq.x / NN - mean * mean; sc = rsqrtf(var + 1e-5f) * ga.x;
    v.x = (v.x - mean) * sc + be.x;
    mean = sm.y / NN; var = sq.y / NN - mean * mean; sc = rsqrtf(var + 1e-5f) * ga.y;
    v.y = (v.y - mean) * sc + be.y;
    mean = sm.z / NN; var = sq.z / NN - mean * mean; sc = rsqrtf(var + 1e-5f) * ga.z;
    v.z = (v.z - mean) * sc + be.z;
    mean = sm.w / NN; var = sq.w / NN - mean * mean; sc = rsqrtf(var + 1e-5f) * ga.w;
    v.w = (v.w - mean) * sc + be.w;
    *(float4*)&out[(size_t)i4 * 4] = v;
}

// ------------------- launch -------------------
extern "C" void kernel_launch(void* const* d_in, const int* in_sizes, int n_in,
                              void* d_out, int out_size) {
    const float* x     = (const float*)d_in[0];
    const void*  ei    = d_in[1];
    const float* W1    = (const float*)d_in[2];
    const float* asrc1 = (const float*)d_in[3];
    const float* adst1 = (const float*)d_in[4];
    const float* g1    = (const float*)d_in[6];
    const float* b1    = (const float*)d_in[7];
    const float* W2    = (const float*)d_in[8];
    const float* asrc2 = (const float*)d_in[9];
    const float* adst2 = (const float*)d_in[10];
    const float* g2    = (const float*)d_in[12];
    const float* b2    = (const float*)d_in[13];
    float* out = (float*)d_out;

    const int T = 256;
    const int EB = (ETOT + T - 1) / T;
    const int SB = (NN + SROWS - 1) / SROWS;

    k_decode<<<EB, T>>>(ei);                                   // decode + count + rank + zero BN
    k_gemm1<<<dim3(HID / 64, (NN + 127) / 128), T>>>(x, W1);   // tf32 wmma
    k_scan<<<1, 256>>>();
    k_fill<<<EB, T>>>();                                       // atomic-free scatter
    k_alpha1<<<(NN * 32 + T - 1) / T, T>>>(asrc1, adst1);
    k_agg1<<<(NN * 64 + T - 1) / T, T>>>();                    // 2 warps per node
    k_stats1<<<SB, 256>>>();
    k_apply1<<<(NN * HID / 4 + T - 1) / T, T>>>(g1, b1);       // float4
    k_gemm2<<<dim3(OUT_DIM / 64, (NN + 127) / 128), T>>>(W2);  // tf32 wmma
    k_alpha2<<<(NN * 32 + T - 1) / T, T>>>(asrc2, adst2);      // + zero BN accums
    k_agg2<<<(NN * 32 + T - 1) / T, T>>>();
    k_stats2<<<SB, 128>>>();
    k_apply2<<<(NN * OUT_DIM / 4 + T - 1) / T, T>>>(g2, b2, out); // float4 + re-zero g_cnt
}